// round 1
// baseline (speedup 1.0000x reference)
#include <cuda_runtime.h>
#include <math.h>

// ---------------- static config ----------------
#define ZD 8
#define HD_G 96
#define WD 192
#define DIMC 192
#define HEADS 6
#define HDIM 32
#define NTOK 144      // tokens per window
#define NWIN 1024     // windows (B=1)
#define TOK 147456    // total tokens
#define WT 64         // window types (NZ*NH)
#define NW 16

// ---------------- device scratch ----------------
static __device__ float g_x[TOK * DIMC];        // current residual stream
static __device__ float g_xw[TOK * DIMC];       // LN output (window order or token order)
static __device__ float g_qkv[TOK * 3 * DIMC];  // qkv in window order
static __device__ float g_attn[TOK * DIMC];     // attention output (window order)
static __device__ float g_hh[TOK * 4 * DIMC];   // mlp hidden
static __device__ float g_bias[WT * HEADS * NTOK * NTOK]; // expanded position bias

// window row -> global token index (also reverse+unroll destination; same formula)
__device__ __forceinline__ int map_index(int r, int rolled) {
    int win = r / NTOK, t = r - win * NTOK;
    int nz = win >> 8;
    int nh = (win >> 4) & 15;
    int nw = win & 15;
    int lz = t / 72;
    int lh = (t / 12) % 6;
    int lw = t % 12;
    int z = nz * 2 + lz, h = nh * 6 + lh, w = nw * 12 + lw;
    if (rolled) {
        z = (z + 1) & 7;
        h += 3; if (h >= 96) h -= 96;
        w += 6; if (w >= 192) w -= 192;
    }
    return (z * 96 + h) * 192 + w;
}

// ---------------- copy ----------------
__global__ void copy_kernel(const float4* __restrict__ src, float4* __restrict__ dst, int n4) {
    int i = blockIdx.x * blockDim.x + threadIdx.x;
    if (i < n4) dst[i] = src[i];
}

// ---------------- LayerNorm (+optional partition/roll) ----------------
// mode 0: identity row order; 1: window partition; 2: window partition with roll
__global__ void ln_kernel(const float* __restrict__ x, const float* __restrict__ w,
                          const float* __restrict__ b, float* __restrict__ out, int mode) {
    int warp = (blockIdx.x * blockDim.x + threadIdx.x) >> 5;
    int lane = threadIdx.x & 31;
    if (warp >= TOK) return;
    int g = (mode == 0) ? warp : map_index(warp, mode == 2);
    const float* xr = x + (size_t)g * DIMC;
    float v[6];
    float s = 0.f;
#pragma unroll
    for (int i = 0; i < 6; i++) { v[i] = xr[lane + 32 * i]; s += v[i]; }
#pragma unroll
    for (int o = 16; o; o >>= 1) s += __shfl_xor_sync(0xffffffffu, s, o);
    float mean = s * (1.f / 192.f);
    float sq = 0.f;
#pragma unroll
    for (int i = 0; i < 6; i++) { float d = v[i] - mean; sq += d * d; }
#pragma unroll
    for (int o = 16; o; o >>= 1) sq += __shfl_xor_sync(0xffffffffu, sq, o);
    float r = rsqrtf(sq * (1.f / 192.f) + 1e-5f);
    float* orow = out + (size_t)warp * DIMC;
#pragma unroll
    for (int i = 0; i < 6; i++) {
        int c = lane + 32 * i;
        orow[c] = (v[i] - mean) * r * w[c] + b[c];
    }
}

// ---------------- expand relative-position bias table ----------------
// out[wt][head][i][j] = bt[pos(i,j)*384 + wt*6 + head]
__global__ void bias_expand(const float* __restrict__ bt, float* __restrict__ out) {
    int idx = blockIdx.x * blockDim.x + threadIdx.x;
    if (idx >= WT * HEADS * NTOK * NTOK) return;
    int j = idx % 144;
    int tmp = idx / 144;
    int i = tmp % 144;
    tmp /= 144;
    int head = tmp % 6;
    int wt = tmp / 6;
    int zi = i / 72, hi = (i / 12) % 6, wi = i % 12;
    int zj = j / 72, hj = (j / 12) % 6, wj = j % 12;
    int pos = (zi + 2 * zj) * 828 + (hi + 6 * hj) * 23 + (wi - wj + 11);
    out[idx] = bt[pos * 384 + wt * 6 + head];
}

// ---------------- windowed attention ----------------
// one block per (window, head); 2-pass online softmax, K/V in SMEM
__global__ __launch_bounds__(160) void attn_kernel(int masked) {
    __shared__ float ks[NTOK][HDIM];
    __shared__ float vs[NTOK][HDIM];
    __shared__ int rid[NTOK];
    int bid = blockIdx.x;
    int win = bid / HEADS, head = bid - win * HEADS;
    int wt = win >> 4;
    int t = threadIdx.x;
    size_t base = (size_t)win * NTOK * 576;

    for (int idx = t; idx < NTOK * HDIM; idx += 160) {
        int j = idx >> 5, d = idx & 31;
        size_t ro = base + (size_t)j * 576 + head * 32 + d;
        ks[j][d] = g_qkv[ro + 192];
        vs[j][d] = g_qkv[ro + 384];
    }
    if (masked && t < NTOK) {
        int nz = win >> 8, nh = (win >> 4) & 15, nw = win & 15;
        int lz = t / 72, lh = (t / 12) % 6, lw = t % 12;
        int z = nz * 2 + lz, h = nh * 6 + lh, w = nw * 12 + lw;
        int rz = z < 6 ? 0 : (z < 7 ? 1 : 2);
        int rh = h < 90 ? 0 : (h < 93 ? 1 : 2);
        int rw = w < 180 ? 0 : (w < 186 ? 1 : 2);
        rid[t] = rz * 9 + rh * 3 + rw;
    }
    __syncthreads();
    if (t >= NTOK) return;

    const float scale = 0.17677669529663687f; // 32^-0.5
    float q[HDIM];
#pragma unroll
    for (int d = 0; d < HDIM; d++) q[d] = g_qkv[base + (size_t)t * 576 + head * 32 + d] * scale;

    const float* brow = g_bias + (((size_t)(wt * HEADS + head) * NTOK) + t) * NTOK;
    int myrid = masked ? rid[t] : 0;

    float mx = -1e30f;
    for (int j = 0; j < NTOK; j++) {
        float s = brow[j];
#pragma unroll
        for (int d = 0; d < HDIM; d++) s += q[d] * ks[j][d];
        if (masked && rid[j] != myrid) s -= 100.f;
        mx = fmaxf(mx, s);
    }
    float sum = 0.f;
    float o[HDIM];
#pragma unroll
    for (int d = 0; d < HDIM; d++) o[d] = 0.f;
    for (int j = 0; j < NTOK; j++) {
        float s = brow[j];
#pragma unroll
        for (int d = 0; d < HDIM; d++) s += q[d] * ks[j][d];
        if (masked && rid[j] != myrid) s -= 100.f;
        float p = expf(s - mx);
        sum += p;
#pragma unroll
        for (int d = 0; d < HDIM; d++) o[d] += p * vs[j][d];
    }
    float inv = 1.f / sum;
    float* orow = g_attn + ((size_t)win * NTOK + t) * DIMC + head * 32;
#pragma unroll
    for (int d = 0; d < HDIM; d++) orow[d] = o[d] * inv;
}

// ---------------- fp32 GEMM, 128x64x16 tiles, 8x4 per thread ----------------
// EPI 0: C = A*B + bias                     (qkv)
// EPI 1: C = gelu(A*B + bias)               (mlp1)
// EPI 2: C[map(row)] += A*B + bias          (proj: reverse + unroll + residual, N==192)
// EPI 3: C = resid + A*B + bias             (mlp2 residual, dest may be d_out)
template <int EPI>
__global__ __launch_bounds__(256) void gemm_kernel(
    const float* __restrict__ A, const float* __restrict__ Bm,
    const float* __restrict__ bias, float* __restrict__ C,
    const float* __restrict__ resid, int M, int N, int K, int rolled) {
    __shared__ float As[16][132];
    __shared__ float Bs[16][68];
    int tid = threadIdx.x;
    int tx = tid & 15, ty = tid >> 4;
    int bm = blockIdx.y * 128, bn = blockIdx.x * 64;
    float acc[8][4];
#pragma unroll
    for (int i = 0; i < 8; i++)
#pragma unroll
        for (int j = 0; j < 4; j++) acc[i][j] = 0.f;

    for (int k0 = 0; k0 < K; k0 += 16) {
#pragma unroll
        for (int i = 0; i < 2; i++) {
            int idx = tid + i * 256;
            int row = idx >> 2, q = (idx & 3) * 4;
            float4 av = *(const float4*)(A + (size_t)(bm + row) * K + k0 + q);
            As[q + 0][row] = av.x;
            As[q + 1][row] = av.y;
            As[q + 2][row] = av.z;
            As[q + 3][row] = av.w;
        }
        {
            int krow = tid >> 4, qc = (tid & 15) * 4;
            float4 bv = *(const float4*)(Bm + (size_t)(k0 + krow) * N + bn + qc);
            *(float4*)&Bs[krow][qc] = bv;
        }
        __syncthreads();
#pragma unroll
        for (int kk = 0; kk < 16; kk++) {
            float a[8], b[4];
            *(float4*)&a[0] = *(const float4*)&As[kk][ty * 8];
            *(float4*)&a[4] = *(const float4*)&As[kk][ty * 8 + 4];
            *(float4*)&b[0] = *(const float4*)&Bs[kk][tx * 4];
#pragma unroll
            for (int i = 0; i < 8; i++)
#pragma unroll
                for (int j = 0; j < 4; j++) acc[i][j] += a[i] * b[j];
        }
        __syncthreads();
    }

#pragma unroll
    for (int i = 0; i < 8; i++) {
        int row = bm + ty * 8 + i;
        if (EPI == 2) {
            int g = map_index(row, rolled);
            float* crow = C + (size_t)g * 192;
#pragma unroll
            for (int j = 0; j < 4; j++) {
                int col = bn + tx * 4 + j;
                crow[col] += acc[i][j] + bias[col];
            }
        } else {
            size_t off = (size_t)row * N;
#pragma unroll
            for (int j = 0; j < 4; j++) {
                int col = bn + tx * 4 + j;
                float val = acc[i][j] + bias[col];
                if (EPI == 1) val = 0.5f * val * (1.0f + erff(val * 0.70710678118654752f));
                if (EPI == 3) val += resid[off + col];
                C[off + col] = val;
            }
        }
    }
}

// ---------------- launch ----------------
extern "C" void kernel_launch(void* const* d_in, const int* in_sizes, int n_in,
                              void* d_out, int out_size) {
    const float* x_in = (const float*)d_in[0];
    const float* n1w = (const float*)d_in[1];
    const float* n1b = (const float*)d_in[2];
    const float* qw  = (const float*)d_in[3];
    const float* qb  = (const float*)d_in[4];
    const float* bt  = (const float*)d_in[5];
    const float* pw  = (const float*)d_in[6];
    const float* pb  = (const float*)d_in[7];
    const float* n2w = (const float*)d_in[8];
    const float* n2b = (const float*)d_in[9];
    const float* w1  = (const float*)d_in[10];
    const float* b1  = (const float*)d_in[11];
    const float* w2  = (const float*)d_in[12];
    const float* b2  = (const float*)d_in[13];
    float* out = (float*)d_out;

    float *px, *pxw, *pqkv, *pattn, *phh, *pbias;
    cudaGetSymbolAddress((void**)&px, g_x);
    cudaGetSymbolAddress((void**)&pxw, g_xw);
    cudaGetSymbolAddress((void**)&pqkv, g_qkv);
    cudaGetSymbolAddress((void**)&pattn, g_attn);
    cudaGetSymbolAddress((void**)&phh, g_hh);
    cudaGetSymbolAddress((void**)&pbias, g_bias);

    // x -> g_x
    {
        int n4 = TOK * DIMC / 4;
        copy_kernel<<<(n4 + 255) / 256, 256>>>((const float4*)x_in, (float4*)px, n4);
    }

    const int LN_GRID = TOK / 8; // 8 warps per 256-thread block

    for (int blk = 0; blk < 2; blk++) {
        int rolled = blk; // block 1 is shifted/masked
        // expand relative position bias
        {
            int n = WT * HEADS * NTOK * NTOK;
            bias_expand<<<(n + 255) / 256, 256>>>(bt + (size_t)blk * 3312 * 384, pbias);
        }
        // LN1 + partition(+roll)
        ln_kernel<<<LN_GRID, 256>>>(px, n1w + blk * DIMC, n1b + blk * DIMC, pxw, rolled ? 2 : 1);
        // QKV GEMM: (TOK,192) @ (192,576)
        gemm_kernel<0><<<dim3(576 / 64, TOK / 128), 256>>>(
            pxw, qw + (size_t)blk * DIMC * 576, qb + blk * 576, pqkv, nullptr, TOK, 576, DIMC, 0);
        // attention per (window, head)
        attn_kernel<<<NWIN * HEADS, 160>>>(rolled);
        // proj GEMM + reverse + unroll + residual add into g_x
        gemm_kernel<2><<<dim3(192 / 64, TOK / 128), 256>>>(
            pattn, pw + (size_t)blk * DIMC * DIMC, pb + blk * DIMC, px, nullptr, TOK, DIMC, DIMC, rolled);
        // LN2 (token order)
        ln_kernel<<<LN_GRID, 256>>>(px, n2w + blk * DIMC, n2b + blk * DIMC, pxw, 0);
        // MLP1 GEMM + exact GELU
        gemm_kernel<1><<<dim3(768 / 64, TOK / 128), 256>>>(
            pxw, w1 + (size_t)blk * DIMC * 768, b1 + blk * 768, phh, nullptr, TOK, 768, DIMC, 0);
        // MLP2 GEMM + residual; final block writes straight to d_out
        float* dest = (blk == 1) ? out : px;
        gemm_kernel<3><<<dim3(192 / 64, TOK / 128), 256>>>(
            phh, w2 + (size_t)blk * 768 * DIMC, b2 + blk * DIMC, dest, px, TOK, DIMC, 768, 0);
    }
}

// round 3
// speedup vs baseline: 1.2622x; 1.2622x over previous
#include <cuda_runtime.h>
#include <cuda_bf16.h>
#include <math.h>
#include <stdint.h>

// ---------------- static config ----------------
#define DIMC 192
#define HEADS 6
#define NTOK 144
#define NWIN 1024
#define TOK 147456
#define WT 64

// ---------------- device scratch ----------------
static __device__ float g_x[TOK * DIMC];
static __device__ float g_qkv[TOK * 3 * DIMC];
static __device__ float g_bias[WT * HEADS * NTOK * NTOK];
static __device__ __nv_bfloat16 g_a1h[TOK * DIMC];
static __device__ __nv_bfloat16 g_a1l[TOK * DIMC];
static __device__ __nv_bfloat16 g_a2h[TOK * 4 * DIMC];
static __device__ __nv_bfloat16 g_a2l[TOK * 4 * DIMC];
static __device__ __nv_bfloat16 g_wh[768 * DIMC];
static __device__ __nv_bfloat16 g_wl[768 * DIMC];

__device__ __forceinline__ uint32_t smem_u32(const void* p) {
    uint32_t a;
    asm("{ .reg .u64 t; cvta.to.shared.u64 t, %1; cvt.u32.u64 %0, t; }" : "=r"(a) : "l"(p));
    return a;
}

#define LDSM_X4(r0, r1, r2, r3, a) \
    asm volatile("ldmatrix.sync.aligned.m8n8.x4.shared.b16 {%0,%1,%2,%3}, [%4];" \
                 : "=r"(r0), "=r"(r1), "=r"(r2), "=r"(r3) : "r"(a))
#define LDSM_X4_T(r0, r1, r2, r3, a) \
    asm volatile("ldmatrix.sync.aligned.m8n8.x4.trans.shared.b16 {%0,%1,%2,%3}, [%4];" \
                 : "=r"(r0), "=r"(r1), "=r"(r2), "=r"(r3) : "r"(a))
#define MMA16816(d, a0, a1, a2, a3, b0, b1) \
    asm volatile("mma.sync.aligned.m16n8k16.row.col.f32.bf16.bf16.f32 " \
                 "{%0,%1,%2,%3}, {%4,%5,%6,%7}, {%8,%9}, {%0,%1,%2,%3};" \
                 : "+f"((d)[0]), "+f"((d)[1]), "+f"((d)[2]), "+f"((d)[3]) \
                 : "r"(a0), "r"(a1), "r"(a2), "r"(a3), "r"(b0), "r"(b1))
#define CP_ASYNC16(dst, src) \
    asm volatile("cp.async.cg.shared.global [%0], [%1], 16;" :: "r"(dst), "l"(src))
#define CP_COMMIT() asm volatile("cp.async.commit_group;" ::: "memory")
#define CP_WAIT1() asm volatile("cp.async.wait_group 1;" ::: "memory")
#define CP_WAIT0() asm volatile("cp.async.wait_group 0;" ::: "memory")

__device__ __forceinline__ int map_index(int r, int rolled) {
    int win = r / NTOK, t = r - win * NTOK;
    int nz = win >> 8, nh = (win >> 4) & 15, nw = win & 15;
    int lz = t / 72, lh = (t / 12) % 6, lw = t % 12;
    int z = nz * 2 + lz, h = nh * 6 + lh, w = nw * 12 + lw;
    if (rolled) {
        z = (z + 1) & 7;
        h += 3; if (h >= 96) h -= 96;
        w += 6; if (w >= 192) w -= 192;
    }
    return (z * 96 + h) * 192 + w;
}

// ---------------- copy ----------------
__global__ void copy_kernel(const float4* __restrict__ src, float4* __restrict__ dst, int n4) {
    int i = blockIdx.x * blockDim.x + threadIdx.x;
    if (i < n4) dst[i] = src[i];
}

// ---------------- LayerNorm -> bf16 hi/lo ----------------
__global__ void ln_kernel(const float* __restrict__ x, const float* __restrict__ w,
                          const float* __restrict__ b,
                          __nv_bfloat16* __restrict__ oh, __nv_bfloat16* __restrict__ ol, int mode) {
    int warp = (blockIdx.x * blockDim.x + threadIdx.x) >> 5;
    int lane = threadIdx.x & 31;
    if (warp >= TOK) return;
    int g = (mode == 0) ? warp : map_index(warp, mode == 2);
    const float* xr = x + (size_t)g * DIMC;
    float v[6];
    float s = 0.f;
#pragma unroll
    for (int i = 0; i < 6; i++) { v[i] = xr[lane + 32 * i]; s += v[i]; }
#pragma unroll
    for (int o = 16; o; o >>= 1) s += __shfl_xor_sync(0xffffffffu, s, o);
    float mean = s * (1.f / 192.f);
    float sq = 0.f;
#pragma unroll
    for (int i = 0; i < 6; i++) { float d = v[i] - mean; sq += d * d; }
#pragma unroll
    for (int o = 16; o; o >>= 1) sq += __shfl_xor_sync(0xffffffffu, sq, o);
    float r = rsqrtf(sq * (1.f / 192.f) + 1e-5f);
    size_t ro = (size_t)warp * DIMC;
#pragma unroll
    for (int i = 0; i < 6; i++) {
        int c = lane + 32 * i;
        float val = (v[i] - mean) * r * w[c] + b[c];
        __nv_bfloat16 h = __float2bfloat16(val);
        oh[ro + c] = h;
        ol[ro + c] = __float2bfloat16(val - __bfloat162float(h));
    }
}

// ---------------- weight hi/lo split (keeps [K,N] layout) ----------------
__global__ void wconv(const float* __restrict__ w, __nv_bfloat16* __restrict__ hi,
                      __nv_bfloat16* __restrict__ lo, int total) {
    int idx = blockIdx.x * blockDim.x + threadIdx.x;
    if (idx >= total) return;
    float v = w[idx];
    __nv_bfloat16 h = __float2bfloat16(v);
    hi[idx] = h;
    lo[idx] = __float2bfloat16(v - __bfloat162float(h));
}

// ---------------- bias table expansion ----------------
__global__ void bias_expand(const float* __restrict__ bt, float* __restrict__ out) {
    int idx = blockIdx.x * blockDim.x + threadIdx.x;
    if (idx >= WT * HEADS * NTOK * NTOK) return;
    int j = idx % 144;
    int tmp = idx / 144;
    int i = tmp % 144;
    tmp /= 144;
    int head = tmp % 6;
    int wt = tmp / 6;
    int zi = i / 72, hi = (i / 12) % 6, wi = i % 12;
    int zj = j / 72, hj = (j / 12) % 6, wj = j % 12;
    int pos = (zi + 2 * zj) * 828 + (hi + 6 * hj) * 23 + (wi - wj + 11);
    out[idx] = bt[pos * 384 + wt * 6 + head];
}

// ---------------- attention: 2 query rows / thread, bf16 hi/lo out ----------------
__global__ __launch_bounds__(80) void attn_kernel(int masked) {
    __shared__ float4 ks[NTOK][8];
    __shared__ float4 vs[NTOK][8];
    __shared__ int rid[NTOK];
    int bid = blockIdx.x;
    int win = bid / HEADS, head = bid - win * HEADS;
    int wt = win >> 4;
    int t = threadIdx.x;
    size_t base = (size_t)win * NTOK * 576;

    for (int idx = t; idx < NTOK * 8; idx += 80) {
        int j = idx >> 3, d4 = idx & 7;
        const float* ro = g_qkv + base + (size_t)j * 576 + head * 32 + d4 * 4;
        ks[j][d4] = *(const float4*)(ro + 192);
        vs[j][d4] = *(const float4*)(ro + 384);
    }
    if (masked) {
        for (int tt = t; tt < NTOK; tt += 80) {
            int nz = win >> 8, nh = (win >> 4) & 15, nw = win & 15;
            int lz = tt / 72, lh = (tt / 12) % 6, lw = tt % 12;
            int z = nz * 2 + lz, h = nh * 6 + lh, w = nw * 12 + lw;
            int rz = z < 6 ? 0 : (z < 7 ? 1 : 2);
            int rh = h < 90 ? 0 : (h < 93 ? 1 : 2);
            int rw = w < 180 ? 0 : (w < 186 ? 1 : 2);
            rid[tt] = rz * 9 + rh * 3 + rw;
        }
    }
    __syncthreads();
    if (t >= 72) return;
    int i0 = 2 * t, i1 = 2 * t + 1;

    const float scale = 0.17677669529663687f;
    float4 q0[8], q1[8];
#pragma unroll
    for (int d = 0; d < 8; d++) {
        float4 a = *(const float4*)(g_qkv + base + (size_t)i0 * 576 + head * 32 + d * 4);
        float4 b = *(const float4*)(g_qkv + base + (size_t)i1 * 576 + head * 32 + d * 4);
        q0[d] = make_float4(a.x * scale, a.y * scale, a.z * scale, a.w * scale);
        q1[d] = make_float4(b.x * scale, b.y * scale, b.z * scale, b.w * scale);
    }
    const float* brow0 = g_bias + (((size_t)(wt * HEADS + head) * NTOK) + i0) * NTOK;
    const float* brow1 = brow0 + NTOK;
    int r0 = masked ? rid[i0] : 0;
    int r1 = masked ? rid[i1] : 0;

    float mx0 = -1e30f, mx1 = -1e30f;
    for (int j = 0; j < NTOK; j++) {
        float s0 = brow0[j], s1 = brow1[j];
#pragma unroll
        for (int d = 0; d < 8; d++) {
            float4 k = ks[j][d];
            s0 += q0[d].x * k.x + q0[d].y * k.y + q0[d].z * k.z + q0[d].w * k.w;
            s1 += q1[d].x * k.x + q1[d].y * k.y + q1[d].z * k.z + q1[d].w * k.w;
        }
        if (masked) {
            int rj = rid[j];
            if (rj != r0) s0 -= 100.f;
            if (rj != r1) s1 -= 100.f;
        }
        mx0 = fmaxf(mx0, s0);
        mx1 = fmaxf(mx1, s1);
    }
    float sum0 = 0.f, sum1 = 0.f;
    float4 o0[8], o1[8];
#pragma unroll
    for (int d = 0; d < 8; d++) { o0[d] = make_float4(0, 0, 0, 0); o1[d] = make_float4(0, 0, 0, 0); }
    for (int j = 0; j < NTOK; j++) {
        float s0 = brow0[j], s1 = brow1[j];
#pragma unroll
        for (int d = 0; d < 8; d++) {
            float4 k = ks[j][d];
            s0 += q0[d].x * k.x + q0[d].y * k.y + q0[d].z * k.z + q0[d].w * k.w;
            s1 += q1[d].x * k.x + q1[d].y * k.y + q1[d].z * k.z + q1[d].w * k.w;
        }
        if (masked) {
            int rj = rid[j];
            if (rj != r0) s0 -= 100.f;
            if (rj != r1) s1 -= 100.f;
        }
        float p0 = __expf(s0 - mx0), p1 = __expf(s1 - mx1);
        sum0 += p0; sum1 += p1;
#pragma unroll
        for (int d = 0; d < 8; d++) {
            float4 v = vs[j][d];
            o0[d].x += p0 * v.x; o0[d].y += p0 * v.y; o0[d].z += p0 * v.z; o0[d].w += p0 * v.w;
            o1[d].x += p1 * v.x; o1[d].y += p1 * v.y; o1[d].z += p1 * v.z; o1[d].w += p1 * v.w;
        }
    }
    float inv0 = 1.f / sum0, inv1 = 1.f / sum1;
#pragma unroll
    for (int d = 0; d < 8; d++) {
        size_t off0 = ((size_t)win * NTOK + i0) * DIMC + head * 32 + d * 4;
        size_t off1 = off0 + DIMC;
        float vv[8] = {o0[d].x * inv0, o0[d].y * inv0, o0[d].z * inv0, o0[d].w * inv0,
                       o1[d].x * inv1, o1[d].y * inv1, o1[d].z * inv1, o1[d].w * inv1};
#pragma unroll
        for (int c = 0; c < 4; c++) {
            __nv_bfloat16 h = __float2bfloat16(vv[c]);
            g_a1h[off0 + c] = h;
            g_a1l[off0 + c] = __float2bfloat16(vv[c] - __bfloat162float(h));
            __nv_bfloat16 h2 = __float2bfloat16(vv[4 + c]);
            g_a1h[off1 + c] = h2;
            g_a1l[off1 + c] = __float2bfloat16(vv[4 + c] - __bfloat162float(h2));
        }
    }
}

// ---------------- HMMA GEMM: 128x192 CTA tile, bf16 hi/lo 3-pass, fp32 acc ----------------
// A: [M,K] row-major bf16 (hi/lo), W: [K,N] row-major bf16 (hi/lo).
// EPI 0: C[row*Nfull+col] = v + bias[col]
// EPI 1: gelu -> bf16 hi/lo at stride 768
// EPI 2: C[map(row)*192+col] += v + bias
// EPI 3: C[row*192+col] = v + bias + resid
#define SA_OFF(buf) ((buf) * 16384)
#define SB_OFF(buf) (32768 + (buf) * 24576)
#define GSMEM 81920

template <int EPI>
__global__ __launch_bounds__(256) void hmma_gemm(
    const __nv_bfloat16* __restrict__ a_hi, const __nv_bfloat16* __restrict__ a_lo,
    const __nv_bfloat16* __restrict__ b_hi, const __nv_bfloat16* __restrict__ b_lo,
    const float* __restrict__ bias, float* __restrict__ C, const float* __restrict__ resid,
    __nv_bfloat16* __restrict__ out_hi, __nv_bfloat16* __restrict__ out_lo,
    int K, int Nfull, int rolled)
{
    extern __shared__ char smem[];
    uint32_t sb = smem_u32(smem);
    int tid = threadIdx.x;
    int warp = tid >> 5, lane = tid & 31;
    int wm = warp & 1, wn = warp >> 1;       // warp grid 2 x 4 -> 64x48 per warp
    int bm = blockIdx.y * 128, bn = blockIdx.x * 192;

    int kchunks = K >> 6;
    int nch = 3 * kchunks;

    float acc[4][6][4];
#pragma unroll
    for (int i = 0; i < 4; i++)
#pragma unroll
        for (int j = 0; j < 6; j++)
#pragma unroll
            for (int q = 0; q < 4; q++) acc[i][j][q] = 0.f;

    // prefetch helper (inlined twice)
#define PREFETCH(cidx)                                                                   \
    do {                                                                                 \
        int pass = (cidx) / kchunks;                                                     \
        int kc = ((cidx) - pass * kchunks) << 6;                                         \
        const __nv_bfloat16* Ap = (pass == 1) ? a_lo : a_hi;                             \
        const __nv_bfloat16* Bp = (pass == 2) ? b_lo : b_hi;                             \
        uint32_t ab = sb + SA_OFF((cidx) & 1);                                           \
        uint32_t bb = sb + SB_OFF((cidx) & 1);                                           \
        _Pragma("unroll")                                                                \
        for (int i = 0; i < 4; i++) {                                                    \
            int idx = tid + i * 256;                                                     \
            int r = idx >> 3, c16 = idx & 7;                                             \
            const __nv_bfloat16* src = Ap + (size_t)(bm + r) * K + kc + c16 * 8;         \
            CP_ASYNC16(ab + r * 128 + (c16 ^ (r & 7)) * 16, src);                        \
        }                                                                                \
        _Pragma("unroll")                                                                \
        for (int i = 0; i < 6; i++) {                                                    \
            int idx = tid + i * 256;                                                     \
            int kk = idx / 24, n16 = idx - kk * 24;                                      \
            const __nv_bfloat16* src = Bp + (size_t)(kc + kk) * Nfull + bn + n16 * 8;    \
            int n16s = (n16 & ~7) | ((n16 & 7) ^ (kk & 7));                              \
            CP_ASYNC16(bb + kk * 384 + n16s * 16, src);                                  \
        }                                                                                \
        CP_COMMIT();                                                                     \
    } while (0)

    PREFETCH(0);
    int li = lane >> 3, lr = lane & 7;       // ldmatrix lane decomposition
    int mlane = (li & 1) * 8 + lr;           // A row within 16-tile
    int khalf = li >> 1;                     // A k-half (0/1)
    int klb = (li & 1) * 8 + lr;             // B k within 16
    int nhalf = li >> 1;                     // B n-half

    for (int c = 0; c < nch; c++) {
        if (c + 1 < nch) { PREFETCH(c + 1); CP_WAIT1(); }
        else { CP_WAIT0(); }
        __syncthreads();
        uint32_t ab = sb + SA_OFF(c & 1);
        uint32_t bb = sb + SB_OFF(c & 1);
#pragma unroll
        for (int ks = 0; ks < 4; ks++) {
            uint32_t afr[4][4];
#pragma unroll
            for (int mt = 0; mt < 4; mt++) {
                int m = wm * 64 + mt * 16 + mlane;
                uint32_t addr = ab + m * 128 + (((ks * 2 + khalf) ^ lr) & 7) * 16;
                LDSM_X4(afr[mt][0], afr[mt][1], afr[mt][2], afr[mt][3], addr);
            }
            uint32_t bfr[3][4];
#pragma unroll
            for (int p = 0; p < 3; p++) {
                int kk = ks * 16 + klb;
                int n16 = wn * 6 + p * 2 + nhalf;
                int n16s = (n16 & ~7) | ((n16 & 7) ^ (kk & 7));
                uint32_t addr = bb + kk * 384 + n16s * 16;
                LDSM_X4_T(bfr[p][0], bfr[p][1], bfr[p][2], bfr[p][3], addr);
            }
#pragma unroll
            for (int mt = 0; mt < 4; mt++)
#pragma unroll
                for (int p = 0; p < 3; p++) {
                    MMA16816(acc[mt][p * 2], afr[mt][0], afr[mt][1], afr[mt][2], afr[mt][3],
                             bfr[p][0], bfr[p][1]);
                    MMA16816(acc[mt][p * 2 + 1], afr[mt][0], afr[mt][1], afr[mt][2], afr[mt][3],
                             bfr[p][2], bfr[p][3]);
                }
        }
        __syncthreads();
    }
#undef PREFETCH

    // ---------------- epilogue ----------------
    int row0 = lane >> 2, col0 = (lane & 3) * 2;
#pragma unroll
    for (int mt = 0; mt < 4; mt++) {
#pragma unroll
        for (int half = 0; half < 2; half++) {
            int row = bm + wm * 64 + mt * 16 + row0 + half * 8;
            int gdest = (EPI == 2) ? map_index(row, rolled) : row;
#pragma unroll
            for (int nt = 0; nt < 6; nt++) {
                int col = bn + wn * 48 + nt * 8 + col0;
                float v0 = acc[mt][nt][half * 2 + 0] + bias[col];
                float v1 = acc[mt][nt][half * 2 + 1] + bias[col + 1];
                if (EPI == 0) {
                    float2* p = (float2*)(C + (size_t)row * Nfull + col);
                    *p = make_float2(v0, v1);
                } else if (EPI == 1) {
                    v0 = 0.5f * v0 * (1.0f + erff(v0 * 0.70710678118654752f));
                    v1 = 0.5f * v1 * (1.0f + erff(v1 * 0.70710678118654752f));
                    size_t o = (size_t)row * 768 + col;
                    __nv_bfloat16 h0 = __float2bfloat16(v0);
                    __nv_bfloat16 h1 = __float2bfloat16(v1);
                    __nv_bfloat162* ph = (__nv_bfloat162*)(out_hi + o);
                    *ph = __nv_bfloat162(h0, h1);
                    __nv_bfloat162* pl = (__nv_bfloat162*)(out_lo + o);
                    *pl = __nv_bfloat162(__float2bfloat16(v0 - __bfloat162float(h0)),
                                         __float2bfloat16(v1 - __bfloat162float(h1)));
                } else if (EPI == 2) {
                    float2* p = (float2*)(C + (size_t)gdest * 192 + col);
                    float2 old = *p;
                    *p = make_float2(old.x + v0, old.y + v1);
                } else {
                    size_t o = (size_t)row * 192 + col;
                    float2 r = *(const float2*)(resid + o);
                    *(float2*)(C + o) = make_float2(v0 + r.x, v1 + r.y);
                }
            }
        }
    }
}

// ---------------- launch ----------------
extern "C" void kernel_launch(void* const* d_in, const int* in_sizes, int n_in,
                              void* d_out, int out_size) {
    const float* x_in = (const float*)d_in[0];
    const float* n1w = (const float*)d_in[1];
    const float* n1b = (const float*)d_in[2];
    const float* qw  = (const float*)d_in[3];
    const float* qb  = (const float*)d_in[4];
    const float* bt  = (const float*)d_in[5];
    const float* pw  = (const float*)d_in[6];
    const float* pb  = (const float*)d_in[7];
    const float* n2w = (const float*)d_in[8];
    const float* n2b = (const float*)d_in[9];
    const float* w1  = (const float*)d_in[10];
    const float* b1  = (const float*)d_in[11];
    const float* w2  = (const float*)d_in[12];
    const float* b2  = (const float*)d_in[13];
    float* out = (float*)d_out;

    static int attr_done = 0;
    if (!attr_done) {
        cudaFuncSetAttribute(hmma_gemm<0>, cudaFuncAttributeMaxDynamicSharedMemorySize, GSMEM);
        cudaFuncSetAttribute(hmma_gemm<1>, cudaFuncAttributeMaxDynamicSharedMemorySize, GSMEM);
        cudaFuncSetAttribute(hmma_gemm<2>, cudaFuncAttributeMaxDynamicSharedMemorySize, GSMEM);
        cudaFuncSetAttribute(hmma_gemm<3>, cudaFuncAttributeMaxDynamicSharedMemorySize, GSMEM);
        attr_done = 1;
    }

    float *px, *pqkv, *pbias;
    __nv_bfloat16 *pa1h, *pa1l, *pa2h, *pa2l, *pwh, *pwl;
    cudaGetSymbolAddress((void**)&px, g_x);
    cudaGetSymbolAddress((void**)&pqkv, g_qkv);
    cudaGetSymbolAddress((void**)&pbias, g_bias);
    cudaGetSymbolAddress((void**)&pa1h, g_a1h);
    cudaGetSymbolAddress((void**)&pa1l, g_a1l);
    cudaGetSymbolAddress((void**)&pa2h, g_a2h);
    cudaGetSymbolAddress((void**)&pa2l, g_a2l);
    cudaGetSymbolAddress((void**)&pwh, g_wh);
    cudaGetSymbolAddress((void**)&pwl, g_wl);

    {
        int n4 = TOK * DIMC / 4;
        copy_kernel<<<(n4 + 255) / 256, 256>>>((const float4*)x_in, (float4*)px, n4);
    }

    const int LN_GRID = TOK / 8;
    const int MB = TOK / 128; // 1152

    for (int blk = 0; blk < 2; blk++) {
        int rolled = blk;
        {
            int n = WT * HEADS * NTOK * NTOK;
            bias_expand<<<(n + 255) / 256, 256>>>(bt + (size_t)blk * 3312 * 384, pbias);
        }
        // LN1 + partition(+roll)
        ln_kernel<<<LN_GRID, 256>>>(px, n1w + blk * DIMC, n1b + blk * DIMC, pa1h, pa1l, rolled ? 2 : 1);
        // QKV: (TOK,192)@(192,576)
        wconv<<<(192 * 576 + 255) / 256, 256>>>(qw + (size_t)blk * DIMC * 576, pwh, pwl, 192 * 576);
        hmma_gemm<0><<<dim3(3, MB), 256, GSMEM>>>(
            pa1h, pa1l, pwh, pwl, qb + blk * 576, pqkv, nullptr, nullptr, nullptr, 192, 576, 0);
        // attention
        attn_kernel<<<NWIN * HEADS, 80>>>(rolled);
        // proj + reverse/unroll + residual
        wconv<<<(192 * 192 + 255) / 256, 256>>>(pw + (size_t)blk * DIMC * DIMC, pwh, pwl, 192 * 192);
        hmma_gemm<2><<<dim3(1, MB), 256, GSMEM>>>(
            pa1h, pa1l, pwh, pwl, pb + blk * DIMC, px, nullptr, nullptr, nullptr, 192, 192, rolled);
        // LN2
        ln_kernel<<<LN_GRID, 256>>>(px, n2w + blk * DIMC, n2b + blk * DIMC, pa1h, pa1l, 0);
        // MLP1 + GELU
        wconv<<<(192 * 768 + 255) / 256, 256>>>(w1 + (size_t)blk * DIMC * 768, pwh, pwl, 192 * 768);
        hmma_gemm<1><<<dim3(4, MB), 256, GSMEM>>>(
            pa1h, pa1l, pwh, pwl, b1 + blk * 768, nullptr, nullptr, pa2h, pa2l, 192, 768, 0);
        // MLP2 + residual
        wconv<<<(768 * 192 + 255) / 256, 256>>>(w2 + (size_t)blk * 768 * DIMC, pwh, pwl, 768 * 192);
        float* dest = (blk == 1) ? out : px;
        hmma_gemm<3><<<dim3(1, MB), 256, GSMEM>>>(
            pa2h, pa2l, pwh, pwl, b2 + blk * DIMC, dest, px, nullptr, nullptr, 768, 192, 0);
    }
}

// round 8
// speedup vs baseline: 2.5925x; 2.0539x over previous
#include <cuda_runtime.h>
#include <cuda_fp16.h>
#include <math.h>
#include <stdint.h>

// ---------------- static config ----------------
#define DIMC 192
#define HEADS 6
#define NTOK 144
#define NWIN 1024
#define TOK 147456
#define WT 64

// ---------------- device scratch ----------------
static __device__ float g_x[TOK * DIMC];
static __device__ float g_qkv[TOK * 3 * DIMC];
static __device__ float g_bias[WT * HEADS * NTOK * NTOK];   // layout [wt][head][j][i]
static __device__ __half g_a1[TOK * DIMC];
static __device__ __half g_a2[TOK * 4 * DIMC];
static __device__ __half g_w[768 * DIMC];

__device__ __forceinline__ uint32_t smem_u32(const void* p) {
    uint32_t a;
    asm("{ .reg .u64 t; cvta.to.shared.u64 t, %1; cvt.u32.u64 %0, t; }" : "=r"(a) : "l"(p));
    return a;
}

#define LDSM_X4(r0, r1, r2, r3, a) \
    asm volatile("ldmatrix.sync.aligned.m8n8.x4.shared.b16 {%0,%1,%2,%3}, [%4];" \
                 : "=r"(r0), "=r"(r1), "=r"(r2), "=r"(r3) : "r"(a))
#define LDSM_X4_T(r0, r1, r2, r3, a) \
    asm volatile("ldmatrix.sync.aligned.m8n8.x4.trans.shared.b16 {%0,%1,%2,%3}, [%4];" \
                 : "=r"(r0), "=r"(r1), "=r"(r2), "=r"(r3) : "r"(a))
#define MMA16816(d, a0, a1, a2, a3, b0, b1) \
    asm volatile("mma.sync.aligned.m16n8k16.row.col.f32.f16.f16.f32 " \
                 "{%0,%1,%2,%3}, {%4,%5,%6,%7}, {%8,%9}, {%0,%1,%2,%3};" \
                 : "+f"((d)[0]), "+f"((d)[1]), "+f"((d)[2]), "+f"((d)[3]) \
                 : "r"(a0), "r"(a1), "r"(a2), "r"(a3), "r"(b0), "r"(b1))
#define CP_ASYNC16(dst, src) \
    asm volatile("cp.async.cg.shared.global [%0], [%1], 16;" :: "r"(dst), "l"(src))
#define CP_COMMIT() asm volatile("cp.async.commit_group;" ::: "memory")
#define CP_WAIT1() asm volatile("cp.async.wait_group 1;" ::: "memory")
#define CP_WAIT0() asm volatile("cp.async.wait_group 0;" ::: "memory")

__device__ __forceinline__ int map_index(int r, int rolled) {
    int win = r / NTOK, t = r - win * NTOK;
    int nz = win >> 8, nh = (win >> 4) & 15, nw = win & 15;
    int lz = t / 72, lh = (t / 12) % 6, lw = t % 12;
    int z = nz * 2 + lz, h = nh * 6 + lh, w = nw * 12 + lw;
    if (rolled) {
        z = (z + 1) & 7;
        h += 3; if (h >= 96) h -= 96;
        w += 6; if (w >= 192) w -= 192;
    }
    return (z * 96 + h) * 192 + w;
}

// ---------------- copy ----------------
__global__ void copy_kernel(const float4* __restrict__ src, float4* __restrict__ dst, int n4) {
    int i = blockIdx.x * blockDim.x + threadIdx.x;
    if (i < n4) dst[i] = src[i];
}

// ---------------- LayerNorm -> fp16 ----------------
__global__ void ln_kernel(const float* __restrict__ x, const float* __restrict__ w,
                          const float* __restrict__ b, __half* __restrict__ o, int mode) {
    int warp = (blockIdx.x * blockDim.x + threadIdx.x) >> 5;
    int lane = threadIdx.x & 31;
    if (warp >= TOK) return;
    int g = (mode == 0) ? warp : map_index(warp, mode == 2);
    const float* xr = x + (size_t)g * DIMC;
    float v[6];
    float s = 0.f;
#pragma unroll
    for (int i = 0; i < 6; i++) { v[i] = xr[lane + 32 * i]; s += v[i]; }
#pragma unroll
    for (int of = 16; of; of >>= 1) s += __shfl_xor_sync(0xffffffffu, s, of);
    float mean = s * (1.f / 192.f);
    float sq = 0.f;
#pragma unroll
    for (int i = 0; i < 6; i++) { float d = v[i] - mean; sq += d * d; }
#pragma unroll
    for (int of = 16; of; of >>= 1) sq += __shfl_xor_sync(0xffffffffu, sq, of);
    float r = rsqrtf(sq * (1.f / 192.f) + 1e-5f);
    size_t ro = (size_t)warp * DIMC;
#pragma unroll
    for (int i = 0; i < 6; i++) {
        int c = lane + 32 * i;
        o[ro + c] = __float2half_rn((v[i] - mean) * r * w[c] + b[c]);
    }
}

// ---------------- weight -> fp16 ----------------
__global__ void wconv(const float* __restrict__ w, __half* __restrict__ o, int total) {
    int idx = blockIdx.x * blockDim.x + threadIdx.x;
    if (idx < total) o[idx] = __float2half_rn(w[idx]);
}

// ---------------- bias table expansion (transposed: [wt][head][j][i]) ----------------
__global__ void bias_expand(const float* __restrict__ bt, float* __restrict__ out) {
    int idx = blockIdx.x * blockDim.x + threadIdx.x;
    if (idx >= WT * HEADS * NTOK * NTOK) return;
    int i = idx % 144;          // query row (innermost now)
    int tmp = idx / 144;
    int j = tmp % 144;          // key col
    tmp /= 144;
    int head = tmp % 6;
    int wt = tmp / 6;
    int zi = i / 72, hi = (i / 12) % 6, wi = i % 12;
    int zj = j / 72, hj = (j / 12) % 6, wj = j % 12;
    int pos = (zi + 2 * zj) * 828 + (hi + 6 * hj) * 23 + (wi - wj + 11);
    out[idx] = bt[pos * 384 + wt * 6 + head];
}

// ---------------- attention: single-pass softmax (no max), 2 rows/thread ----------------
__global__ __launch_bounds__(80) void attn_kernel(int masked) {
    __shared__ float4 ks[NTOK][8];
    __shared__ float4 vs[NTOK][8];
    __shared__ int rid[NTOK];
    int bid = blockIdx.x;
    int win = bid / HEADS, head = bid - win * HEADS;
    int wt = win >> 4;
    int t = threadIdx.x;
    size_t base = (size_t)win * NTOK * 576;

    for (int idx = t; idx < NTOK * 8; idx += 80) {
        int j = idx >> 3, d4 = idx & 7;
        const float* ro = g_qkv + base + (size_t)j * 576 + head * 32 + d4 * 4;
        ks[j][d4] = *(const float4*)(ro + 192);
        vs[j][d4] = *(const float4*)(ro + 384);
    }
    if (masked) {
        for (int tt = t; tt < NTOK; tt += 80) {
            int nz = win >> 8, nh = (win >> 4) & 15, nw = win & 15;
            int lz = tt / 72, lh = (tt / 12) % 6, lw = tt % 12;
            int z = nz * 2 + lz, h = nh * 6 + lh, w = nw * 12 + lw;
            int rz = z < 6 ? 0 : (z < 7 ? 1 : 2);
            int rh = h < 90 ? 0 : (h < 93 ? 1 : 2);
            int rw = w < 180 ? 0 : (w < 186 ? 1 : 2);
            rid[tt] = rz * 9 + rh * 3 + rw;
        }
    }
    __syncthreads();
    if (t >= 72) return;
    int i0 = 2 * t, i1 = 2 * t + 1;

    const float scale = 0.17677669529663687f;
    float4 q0[8], q1[8];
#pragma unroll
    for (int d = 0; d < 8; d++) {
        float4 a = *(const float4*)(g_qkv + base + (size_t)i0 * 576 + head * 32 + d * 4);
        float4 b = *(const float4*)(g_qkv + base + (size_t)i1 * 576 + head * 32 + d * 4);
        q0[d] = make_float4(a.x * scale, a.y * scale, a.z * scale, a.w * scale);
        q1[d] = make_float4(b.x * scale, b.y * scale, b.z * scale, b.w * scale);
    }
    const float* bT = g_bias + (size_t)(wt * HEADS + head) * NTOK * NTOK;
    int r0 = masked ? rid[i0] : 0;
    int r1 = masked ? rid[i1] : 0;

    float sum0 = 0.f, sum1 = 0.f;
    float4 o0[8], o1[8];
#pragma unroll
    for (int d = 0; d < 8; d++) { o0[d] = make_float4(0, 0, 0, 0); o1[d] = make_float4(0, 0, 0, 0); }
    for (int j = 0; j < NTOK; j++) {
        float2 bv = *(const float2*)(bT + (size_t)j * NTOK + i0);
        float s0 = bv.x, s1 = bv.y;
#pragma unroll
        for (int d = 0; d < 8; d++) {
            float4 k = ks[j][d];
            s0 += q0[d].x * k.x + q0[d].y * k.y + q0[d].z * k.z + q0[d].w * k.w;
            s1 += q1[d].x * k.x + q1[d].y * k.y + q1[d].z * k.z + q1[d].w * k.w;
        }
        if (masked) {
            int rj = rid[j];
            if (rj != r0) s0 -= 100.f;
            if (rj != r1) s1 -= 100.f;
        }
        float p0 = __expf(s0), p1 = __expf(s1);
        sum0 += p0; sum1 += p1;
#pragma unroll
        for (int d = 0; d < 8; d++) {
            float4 v = vs[j][d];
            o0[d].x += p0 * v.x; o0[d].y += p0 * v.y; o0[d].z += p0 * v.z; o0[d].w += p0 * v.w;
            o1[d].x += p1 * v.x; o1[d].y += p1 * v.y; o1[d].z += p1 * v.z; o1[d].w += p1 * v.w;
        }
    }
    float inv0 = 1.f / sum0, inv1 = 1.f / sum1;
#pragma unroll
    for (int d = 0; d < 8; d++) {
        size_t off0 = ((size_t)win * NTOK + i0) * DIMC + head * 32 + d * 4;
        size_t off1 = off0 + DIMC;
        __half2* p00 = (__half2*)(g_a1 + off0);
        p00[0] = __floats2half2_rn(o0[d].x * inv0, o0[d].y * inv0);
        p00[1] = __floats2half2_rn(o0[d].z * inv0, o0[d].w * inv0);
        __half2* p10 = (__half2*)(g_a1 + off1);
        p10[0] = __floats2half2_rn(o1[d].x * inv1, o1[d].y * inv1);
        p10[1] = __floats2half2_rn(o1[d].z * inv1, o1[d].w * inv1);
    }
}

// ---------------- HMMA GEMM: 128x192 CTA tile, fp16 single pass, fp32 acc ----------------
// EPI 0: C[row*Nfull+col] = v + bias[col]
// EPI 1: gelu -> fp16, stride 768
// EPI 2: C[map(row)*192+col] += v + bias
// EPI 3: C[row*192+col] = v + bias + resid
#define SA_OFF(buf) ((buf) * 16384)
#define SB_OFF(buf) (32768 + (buf) * 24576)
#define GSMEM 81920

template <int EPI>
__global__ __launch_bounds__(256) void hmma_gemm(
    const __half* __restrict__ A, const __half* __restrict__ Bw,
    const float* __restrict__ bias, float* __restrict__ C, const float* __restrict__ resid,
    __half* __restrict__ outh, int K, int Nfull, int rolled)
{
    extern __shared__ char smem[];
    uint32_t sb = smem_u32(smem);
    int tid = threadIdx.x;
    int warp = tid >> 5, lane = tid & 31;
    int wm = warp & 1, wn = warp >> 1;
    int bm = blockIdx.y * 128, bn = blockIdx.x * 192;
    int nch = K >> 6;

    float acc[4][6][4];
#pragma unroll
    for (int i = 0; i < 4; i++)
#pragma unroll
        for (int j = 0; j < 6; j++)
#pragma unroll
            for (int q = 0; q < 4; q++) acc[i][j][q] = 0.f;

#define PREFETCH(cidx)                                                                   \
    do {                                                                                 \
        int kc = (cidx) << 6;                                                            \
        uint32_t ab = sb + SA_OFF((cidx) & 1);                                           \
        uint32_t bb = sb + SB_OFF((cidx) & 1);                                           \
        _Pragma("unroll")                                                                \
        for (int i = 0; i < 4; i++) {                                                    \
            int idx = tid + i * 256;                                                     \
            int r = idx >> 3, c16 = idx & 7;                                             \
            const __half* src = A + (size_t)(bm + r) * K + kc + c16 * 8;                 \
            CP_ASYNC16(ab + r * 128 + (c16 ^ (r & 7)) * 16, src);                        \
        }                                                                                \
        _Pragma("unroll")                                                                \
        for (int i = 0; i < 6; i++) {                                                    \
            int idx = tid + i * 256;                                                     \
            int kk = idx / 24, n16 = idx - kk * 24;                                      \
            const __half* src = Bw + (size_t)(kc + kk) * Nfull + bn + n16 * 8;           \
            int n16s = (n16 & ~7) | ((n16 & 7) ^ (kk & 7));                              \
            CP_ASYNC16(bb + kk * 384 + n16s * 16, src);                                  \
        }                                                                                \
        CP_COMMIT();                                                                     \
    } while (0)

    PREFETCH(0);
    int li = lane >> 3, lr = lane & 7;
    int mlane = (li & 1) * 8 + lr;
    int khalf = li >> 1;
    int klb = (li & 1) * 8 + lr;
    int nhalf = li >> 1;

    for (int c = 0; c < nch; c++) {
        if (c + 1 < nch) { PREFETCH(c + 1); CP_WAIT1(); }
        else { CP_WAIT0(); }
        __syncthreads();
        uint32_t ab = sb + SA_OFF(c & 1);
        uint32_t bb = sb + SB_OFF(c & 1);
#pragma unroll
        for (int ks = 0; ks < 4; ks++) {
            uint32_t afr[4][4];
#pragma unroll
            for (int mt = 0; mt < 4; mt++) {
                int m = wm * 64 + mt * 16 + mlane;
                uint32_t addr = ab + m * 128 + (((ks * 2 + khalf) ^ lr) & 7) * 16;
                LDSM_X4(afr[mt][0], afr[mt][1], afr[mt][2], afr[mt][3], addr);
            }
            uint32_t bfr[3][4];
#pragma unroll
            for (int p = 0; p < 3; p++) {
                int kk = ks * 16 + klb;
                int n16 = wn * 6 + p * 2 + nhalf;
                int n16s = (n16 & ~7) | ((n16 & 7) ^ (kk & 7));
                uint32_t addr = bb + kk * 384 + n16s * 16;
                LDSM_X4_T(bfr[p][0], bfr[p][1], bfr[p][2], bfr[p][3], addr);
            }
#pragma unroll
            for (int mt = 0; mt < 4; mt++)
#pragma unroll
                for (int p = 0; p < 3; p++) {
                    MMA16816(acc[mt][p * 2], afr[mt][0], afr[mt][1], afr[mt][2], afr[mt][3],
                             bfr[p][0], bfr[p][1]);
                    MMA16816(acc[mt][p * 2 + 1], afr[mt][0], afr[mt][1], afr[mt][2], afr[mt][3],
                             bfr[p][2], bfr[p][3]);
                }
        }
        __syncthreads();
    }
#undef PREFETCH

    int row0 = lane >> 2, col0 = (lane & 3) * 2;
#pragma unroll
    for (int mt = 0; mt < 4; mt++) {
#pragma unroll
        for (int half = 0; half < 2; half++) {
            int row = bm + wm * 64 + mt * 16 + row0 + half * 8;
            int gdest = (EPI == 2) ? map_index(row, rolled) : row;
#pragma unroll
            for (int nt = 0; nt < 6; nt++) {
                int col = bn + wn * 48 + nt * 8 + col0;
                float v0 = acc[mt][nt][half * 2 + 0] + bias[col];
                float v1 = acc[mt][nt][half * 2 + 1] + bias[col + 1];
                if (EPI == 0) {
                    *(float2*)(C + (size_t)row * Nfull + col) = make_float2(v0, v1);
                } else if (EPI == 1) {
                    v0 = 0.5f * v0 * (1.0f + erff(v0 * 0.70710678118654752f));
                    v1 = 0.5f * v1 * (1.0f + erff(v1 * 0.70710678118654752f));
                    *(__half2*)(outh + (size_t)row * 768 + col) = __floats2half2_rn(v0, v1);
                } else if (EPI == 2) {
                    float2* p = (float2*)(C + (size_t)gdest * 192 + col);
                    float2 old = *p;
                    *p = make_float2(old.x + v0, old.y + v1);
                } else {
                    size_t o = (size_t)row * 192 + col;
                    float2 r = *(const float2*)(resid + o);
                    *(float2*)(C + o) = make_float2(v0 + r.x, v1 + r.y);
                }
            }
        }
    }
}

// ---------------- launch ----------------
extern "C" void kernel_launch(void* const* d_in, const int* in_sizes, int n_in,
                              void* d_out, int out_size) {
    const float* x_in = (const float*)d_in[0];
    const float* n1w = (const float*)d_in[1];
    const float* n1b = (const float*)d_in[2];
    const float* qw  = (const float*)d_in[3];
    const float* qb  = (const float*)d_in[4];
    const float* bt  = (const float*)d_in[5];
    const float* pw  = (const float*)d_in[6];
    const float* pb  = (const float*)d_in[7];
    const float* n2w = (const float*)d_in[8];
    const float* n2b = (const float*)d_in[9];
    const float* w1  = (const float*)d_in[10];
    const float* b1  = (const float*)d_in[11];
    const float* w2  = (const float*)d_in[12];
    const float* b2  = (const float*)d_in[13];
    float* out = (float*)d_out;

    static int attr_done = 0;
    if (!attr_done) {
        cudaFuncSetAttribute(hmma_gemm<0>, cudaFuncAttributeMaxDynamicSharedMemorySize, GSMEM);
        cudaFuncSetAttribute(hmma_gemm<1>, cudaFuncAttributeMaxDynamicSharedMemorySize, GSMEM);
        cudaFuncSetAttribute(hmma_gemm<2>, cudaFuncAttributeMaxDynamicSharedMemorySize, GSMEM);
        cudaFuncSetAttribute(hmma_gemm<3>, cudaFuncAttributeMaxDynamicSharedMemorySize, GSMEM);
        attr_done = 1;
    }

    float *px, *pqkv, *pbias;
    __half *pa1, *pa2, *pw16;
    cudaGetSymbolAddress((void**)&px, g_x);
    cudaGetSymbolAddress((void**)&pqkv, g_qkv);
    cudaGetSymbolAddress((void**)&pbias, g_bias);
    cudaGetSymbolAddress((void**)&pa1, g_a1);
    cudaGetSymbolAddress((void**)&pa2, g_a2);
    cudaGetSymbolAddress((void**)&pw16, g_w);

    {
        int n4 = TOK * DIMC / 4;
        copy_kernel<<<(n4 + 255) / 256, 256>>>((const float4*)x_in, (float4*)px, n4);
    }

    const int LN_GRID = TOK / 8;
    const int MB = TOK / 128;

    for (int blk = 0; blk < 2; blk++) {
        int rolled = blk;
        {
            int n = WT * HEADS * NTOK * NTOK;
            bias_expand<<<(n + 255) / 256, 256>>>(bt + (size_t)blk * 3312 * 384, pbias);
        }
        ln_kernel<<<LN_GRID, 256>>>(px, n1w + blk * DIMC, n1b + blk * DIMC, pa1, rolled ? 2 : 1);
        wconv<<<(192 * 576 + 255) / 256, 256>>>(qw + (size_t)blk * DIMC * 576, pw16, 192 * 576);
        hmma_gemm<0><<<dim3(3, MB), 256, GSMEM>>>(
            pa1, pw16, qb + blk * 576, pqkv, nullptr, nullptr, 192, 576, 0);
        attn_kernel<<<NWIN * HEADS, 80>>>(rolled);
        wconv<<<(192 * 192 + 255) / 256, 256>>>(pw + (size_t)blk * DIMC * DIMC, pw16, 192 * 192);
        hmma_gemm<2><<<dim3(1, MB), 256, GSMEM>>>(
            pa1, pw16, pb + blk * DIMC, px, nullptr, nullptr, 192, 192, rolled);
        ln_kernel<<<LN_GRID, 256>>>(px, n2w + blk * DIMC, n2b + blk * DIMC, pa1, 0);
        wconv<<<(192 * 768 + 255) / 256, 256>>>(w1 + (size_t)blk * DIMC * 768, pw16, 192 * 768);
        hmma_gemm<1><<<dim3(4, MB), 256, GSMEM>>>(
            pa1, pw16, b1 + blk * 768, nullptr, nullptr, pa2, 192, 768, 0);
        wconv<<<(768 * 192 + 255) / 256, 256>>>(w2 + (size_t)blk * 768 * DIMC, pw16, 768 * 192);
        float* dest = (blk == 1) ? out : px;
        hmma_gemm<3><<<dim3(1, MB), 256, GSMEM>>>(
            pa2, pw16, b2 + blk * DIMC, dest, px, nullptr, 768, 192, 0);
    }
}